// round 14
// baseline (speedup 1.0000x reference)
#include <cuda_runtime.h>
#include <cuda_fp16.h>
#include <cstdint>
#include <math.h>

#define BQ 4
#define LQ 2048
#define EQ 256
#define HQ 8
#define DH 256     // head dim

// ---------------------------------------------------------------------------
// Scratch (allocation-free device globals, ~132 MB)
// ---------------------------------------------------------------------------
__device__ __half g_xh   [BQ*LQ*EQ];              // x in fp16
__device__ __half g_qh   [BQ*HQ*LQ*DH];           // [bh][l][e], pre-scaled 1/16*log2e
__device__ __half g_kh   [BQ*HQ*LQ*DH];           // [bh][l][e]
__device__ __half g_vh   [BQ*HQ*LQ*DH];           // [bh][l][e] (natural)
__device__ __half g_atth [(size_t)BQ*LQ*HQ*EQ];   // [b][l][h*E+e]
__device__ __half g_wqkvTh[3*HQ*EQ*EQ];           // [6144][256]
__device__ __half g_woutTh[EQ*HQ*EQ];             // [256][2048]

static __device__ __forceinline__ uint32_t smem_u32(const void* p) {
    uint32_t a;
    asm("{ .reg .u64 t; cvta.to.shared.u64 t, %1; cvt.u32.u64 %0, t; }" : "=r"(a) : "l"(p));
    return a;
}
static __device__ __forceinline__ float ex2f(float x) {
    float r; asm("ex2.approx.f32 %0, %1;" : "=f"(r) : "f"(x)); return r;
}
// pack two fp32 -> one b32 reg of f16x2 (lo = a, hi = b)
static __device__ __forceinline__ uint32_t pack_half2(float a, float b) {
    uint32_t u;
    asm("cvt.rn.f16x2.f32 %0, %1, %2;" : "=r"(u) : "f"(b), "f"(a));
    return u;
}
#define CP_ASYNC16(d, s) \
    asm volatile("cp.async.cg.shared.global [%0], [%1], 16;" :: "r"(d), "l"(s))
#define CP_COMMIT() asm volatile("cp.async.commit_group;" ::: "memory")
template<int N> static __device__ __forceinline__ void cp_wait() {
    asm volatile("cp.async.wait_group %0;" :: "n"(N) : "memory");
}
#define LDSM4(r0, r1, r2, r3, a)                                              \
    asm volatile("ldmatrix.sync.aligned.m8n8.x4.shared.b16 {%0,%1,%2,%3}, [%4];" \
        : "=r"(r0), "=r"(r1), "=r"(r2), "=r"(r3) : "r"(a))
#define LDSM4T(r0, r1, r2, r3, a)                                             \
    asm volatile("ldmatrix.sync.aligned.m8n8.x4.trans.shared.b16 {%0,%1,%2,%3}, [%4];" \
        : "=r"(r0), "=r"(r1), "=r"(r2), "=r"(r3) : "r"(a))
#define MMA_F16(c, a0, a1, a2, a3, b0, b1)                                    \
    asm volatile("mma.sync.aligned.m16n8k16.row.col.f32.f16.f16.f32 "         \
        "{%0,%1,%2,%3}, {%4,%5,%6,%7}, {%8,%9}, {%0,%1,%2,%3};"               \
        : "+f"((c)[0]), "+f"((c)[1]), "+f"((c)[2]), "+f"((c)[3])              \
        : "r"(a0), "r"(a1), "r"(a2), "r"(a3), "r"(b0), "r"(b1))

// ---------------------------------------------------------------------------
// Flash attention: one CTA = (bh, 128 q rows). 256 thr, 8 warps x 16 rows.
// Q frags in registers (loaded once); the Q smem region is then DEAD and is
// reused as the 3rd KV buffer: 3-region rotating KV ring, 1 sync per tile.
// KV(t) lives in region (t+1)%3. Region size 2*KVH = Q region size exactly.
// Fixed-base softmax p = exp2(s), 4-chunk S->exp->O interleave per tile.
// ---------------------------------------------------------------------------
#define RQ 128         // q rows per CTA
#define TKV 64         // kv rows per tile
#define SST 264        // smem row stride (halves)
#define KVH (TKV*SST)  // K or V tile halves (16896)
#define REGH (2*KVH)   // one K+V region (33792 halves) == Q region size
#define FLASH_SMEM (3 * REGH * 2)   // 202752 B (unchanged)

__global__ void __launch_bounds__(256)
flash_k()
{
    extern __shared__ __align__(16) __half sm[];
    const int bh = blockIdx.y;
    const int qb = blockIdx.x;
    const __half* Qg = g_qh + (size_t)bh*LQ*DH + (size_t)qb*RQ*DH;
    const __half* Kg = g_kh + (size_t)bh*LQ*DH;
    const __half* Vg = g_vh + (size_t)bh*LQ*DH;

    const int tid = threadIdx.x;
    const uint32_t sbase = smem_u32(sm);

    // ---- load Q into region 0 (async, group 0) ----
    #pragma unroll
    for (int j = 0; j < 16; j++) {
        const int idx = tid + 256*j;
        const int row = idx >> 5, ch = idx & 31;
        CP_ASYNC16(sbase + 2*(uint32_t)(row*SST + ch*8), Qg + (size_t)row*DH + ch*8);
    }
    CP_COMMIT();

    // KV(t) -> region (t+1)%3
    auto issueKV = [&](int t) {
        const int kv0 = t * TKV;
        const uint32_t kb = sbase + 2*(uint32_t)(((t + 1) % 3) * REGH);
        #pragma unroll
        for (int j = 0; j < 8; j++) {
            const int idx = tid + 256*j;
            const int row = idx >> 5, ch = idx & 31;
            CP_ASYNC16(kb + 2*(uint32_t)(row*SST + ch*8),
                       Kg + (size_t)(kv0 + row)*DH + ch*8);
            CP_ASYNC16(kb + 2*(uint32_t)(KVH + row*SST + ch*8),
                       Vg + (size_t)(kv0 + row)*DH + ch*8);
        }
    };
    issueKV(0);            // -> region 1
    CP_COMMIT();

    const int wid = tid >> 5, lane = tid & 31;
    const int grp = lane >> 2, tig = lane & 3;

    const uint32_t aoff = (uint32_t)((wid*16 + (lane & 15)) * SST + (lane >> 4) * 8);
    const uint32_t boff = (uint32_t)(((lane & 7) + ((lane & 16) >> 1)) * SST + (lane & 8));

    // ---- hoist Q fragments into registers (then region 0 becomes free) ----
    cp_wait<1>();          // Q group done; KV(0) may still be in flight
    __syncthreads();
    uint32_t qf[16][4];
    #pragma unroll
    for (int ks = 0; ks < 16; ks++)
        LDSM4(qf[ks][0], qf[ks][1], qf[ks][2], qf[ks][3],
              sbase + 2*(aoff + (uint32_t)(ks*16)));

    issueKV(1);            // -> region 2
    CP_COMMIT();

    float o[32][4];
    #pragma unroll
    for (int j = 0; j < 32; j++)
        #pragma unroll
        for (int i = 0; i < 4; i++) o[j][i] = 0.f;
    float l0 = 0.f, l1 = 0.f;     // per-thread partial row sums

    const int NT = LQ / TKV;   // 32
    for (int t = 0; t < NT; t++) {
        // KV(t) done (newest pending may fly, except at the last tile)
        if (t + 1 < NT) cp_wait<1>(); else cp_wait<0>();
        __syncthreads();   // publishes KV(t) + retires compute(t-1) before the
                           // issue below overwrites region t%3
        if (t + 2 < NT) { issueKV(t + 2); CP_COMMIT(); }

        const uint32_t kb = sbase + 2*(uint32_t)(((t + 1) % 3) * REGH) + 2*boff;
        const uint32_t vb = kb + 2*(uint32_t)KVH;

        // ---- 4 independent 16-KV-row chunks: S -> exp -> pack -> O ----
        #pragma unroll
        for (int kt = 0; kt < 4; kt++) {
            float s0[4] = {0.f, 0.f, 0.f, 0.f};
            float s1[4] = {0.f, 0.f, 0.f, 0.f};
            #pragma unroll
            for (int ks = 0; ks < 16; ks++) {
                uint32_t b0, b1, b2, b3;
                LDSM4(b0, b1, b2, b3, kb + 2*(uint32_t)(kt*16*SST + ks*16));
                MMA_F16(s0, qf[ks][0], qf[ks][1], qf[ks][2], qf[ks][3], b0, b1);
                MMA_F16(s1, qf[ks][0], qf[ks][1], qf[ks][2], qf[ks][3], b2, b3);
            }

            s0[0] = ex2f(s0[0]);  l0 += s0[0];
            s0[1] = ex2f(s0[1]);  l0 += s0[1];
            s0[2] = ex2f(s0[2]);  l1 += s0[2];
            s0[3] = ex2f(s0[3]);  l1 += s0[3];
            s1[0] = ex2f(s1[0]);  l0 += s1[0];
            s1[1] = ex2f(s1[1]);  l0 += s1[1];
            s1[2] = ex2f(s1[2]);  l1 += s1[2];
            s1[3] = ex2f(s1[3]);  l1 += s1[3];

            const uint32_t a0 = pack_half2(s0[0], s0[1]);
            const uint32_t a1 = pack_half2(s0[2], s0[3]);
            const uint32_t a2 = pack_half2(s1[0], s1[1]);
            const uint32_t a3 = pack_half2(s1[2], s1[3]);

            #pragma unroll
            for (int eg = 0; eg < 16; eg++) {
                uint32_t v0, v1, v2, v3;
                LDSM4T(v0, v1, v2, v3, vb + 2*(uint32_t)(kt*16*SST + eg*16));
                MMA_F16(o[2*eg],     a0, a1, a2, a3, v0, v2);
                MMA_F16(o[2*eg + 1], a0, a1, a2, a3, v1, v3);
            }
        }
        // no trailing sync: next iteration's top barrier provides it
    }

    // ---- single final row-sum reduction across the quad ----
    l0 += __shfl_xor_sync(0xffffffffu, l0, 1);
    l0 += __shfl_xor_sync(0xffffffffu, l0, 2);
    l1 += __shfl_xor_sync(0xffffffffu, l1, 1);
    l1 += __shfl_xor_sync(0xffffffffu, l1, 2);
    const float rl0 = 1.f / l0, rl1 = 1.f / l1;

    // ---- epilogue: O /= l, write fp16 concat layout ----
    const int b = bh >> 3, h = bh & 7;
    const int tok0 = qb*RQ + wid*16 + grp;
    uint32_t* base0 = reinterpret_cast<uint32_t*>(
        g_atth + ((size_t)(b*LQ + tok0))*(HQ*EQ) + h*DH);
    uint32_t* base1 = reinterpret_cast<uint32_t*>(
        g_atth + ((size_t)(b*LQ + tok0 + 8))*(HQ*EQ) + h*DH);
    #pragma unroll
    for (int j = 0; j < 32; j++) {
        const int c2 = (j*8 + tig*2) >> 1;   // half2 index within head slice
        base0[c2] = pack_half2(o[j][0]*rl0, o[j][1]*rl0);
        base1[c2] = pack_half2(o[j][2]*rl1, o[j][3]*rl1);
    }
}

// ---------------------------------------------------------------------------
// fp16 mma GEMM: C[M,N] = A[M,K] @ B[N,K]^T  -- 3-stage pipeline
// MODE 0 (BNTT=256): qkv = xh @ WqkvTh^T  scatter q*scale / k / v
// MODE 3 (BNTT=128): out = att @ WoutTh^T -> fp32
// ---------------------------------------------------------------------------
#define BMT 128
#define BKT 32
#define SSTH 40
#define AS_H (128*SSTH)

template<int MODE, int BNTT>
__global__ void __launch_bounds__(256)
tgemm(float* __restrict__ OUT)
{
    constexpr int NT2   = BNTT / 64;
    constexpr int BS_H  = BNTT * SSTH;
    constexpr int STG_B = (AS_H + BS_H) * 2;

    extern __shared__ __align__(16) __half smh[];

    const __half* A; const __half* B; int lda, ldb, K;
    if (MODE == 0) { A = g_xh;   lda = EQ;    B = g_wqkvTh; ldb = EQ;    K = EQ; }
    else           { A = g_atth; lda = HQ*EQ; B = g_woutTh; ldb = HQ*EQ; K = HQ*EQ; }

    const int tid  = threadIdx.x;
    const int rowBase = blockIdx.y * BMT;
    const int colBase = blockIdx.x * BNTT;

    const int lrow  = tid >> 2;
    const int lslot = tid & 3;
    const __half* Ag = A + (size_t)(rowBase + lrow) * lda + lslot * 8;
    const __half* Bg = B + (size_t)(colBase + lrow) * ldb + lslot * 8;
    const uint32_t sbase = smem_u32(smh);
    const uint32_t soff  = (uint32_t)(lrow * SSTH + lslot * 8) * 2;

    const int wid  = tid >> 5, lane = tid & 31;
    const int grp  = lane >> 2, tig = lane & 3;
    const int wm   = (wid >> 2) * 64;
    const int wn   = (wid & 3) * (BNTT / 4);

    const uint32_t aoffh = (uint32_t)((wm + (lane & 15)) * SSTH + ((lane >> 4) * 8));
    const uint32_t boffh = (uint32_t)((wn + (lane & 7) + ((lane & 16) >> 1)) * SSTH + (lane & 8));

    float c[4][NT2][2][4];
    #pragma unroll
    for (int mt = 0; mt < 4; mt++)
        #pragma unroll
        for (int n2 = 0; n2 < NT2; n2++)
            #pragma unroll
            for (int s = 0; s < 2; s++)
                #pragma unroll
                for (int i = 0; i < 4; i++) c[mt][n2][s][i] = 0.f;

    const int nk = K / BKT;

    auto issue = [&](int kt, int st) {
        const int k0 = kt * BKT;
        const uint32_t dA = sbase + st * STG_B + soff;
        CP_ASYNC16(dA,             Ag + k0);
        CP_ASYNC16(dA + 2*64*SSTH, Ag + k0 + (size_t)64 * lda);
        const uint32_t dB = sbase + st * STG_B + 2*AS_H + soff;
        #pragma unroll
        for (int i = 0; i < BNTT/64; i++)
            CP_ASYNC16(dB + i*2*64*SSTH, Bg + k0 + (size_t)(64*i) * ldb);
    };
    auto compute = [&](int st) {
        const uint32_t ab = sbase + st * STG_B + 2*aoffh;
        const uint32_t bb = sbase + st * STG_B + 2*AS_H + 2*boffh;
        #pragma unroll
        for (int ks = 0; ks < 2; ks++) {
            uint32_t af[4][4];
            #pragma unroll
            for (int mt = 0; mt < 4; mt++)
                LDSM4(af[mt][0], af[mt][1], af[mt][2], af[mt][3],
                      ab + 2*(uint32_t)(mt*16*SSTH + ks*16));
            #pragma unroll
            for (int n2 = 0; n2 < NT2; n2++) {
                uint32_t b0, b1, b2, b3;
                LDSM4(b0, b1, b2, b3, bb + 2*(uint32_t)(n2*16*SSTH + ks*16));
                #pragma unroll
                for (int mt = 0; mt < 4; mt++) {
                    MMA_F16(c[mt][n2][0], af[mt][0], af[mt][1], af[mt][2], af[mt][3], b0, b1);
                    MMA_F16(c[mt][n2][1], af[mt][0], af[mt][1], af[mt][2], af[mt][3], b2, b3);
                }
            }
        }
    };

    // 3-stage pipeline: stages kt%3; one sync per iteration.
    issue(0, 0); CP_COMMIT();
    issue(1, 1); CP_COMMIT();
    for (int kt = 0; kt < nk; kt++) {
        if (kt == nk - 1) cp_wait<0>(); else cp_wait<1>();
        __syncthreads();
        if (kt + 2 < nk) { issue(kt + 2, (kt + 2) % 3); CP_COMMIT(); }
        compute(kt % 3);
    }

    #pragma unroll
    for (int mt = 0; mt < 4; mt++) {
        #pragma unroll
        for (int n2 = 0; n2 < NT2; n2++) {
            #pragma unroll
            for (int s = 0; s < 2; s++) {
                const int row0 = rowBase + wm + mt*16 + grp;
                const int cloc = wn + (n2*2 + s)*8 + tig*2;
                const float* cc = c[mt][n2][s];

                if (MODE == 0) {
                    const int part = colBase >> 11;
                    const int h    = (colBase >> 8) & 7;
                    const int e    = cloc;
                    const float qs = 0.0625f * 1.44269504f;   // 1/sqrt(256)*log2(e)
                    #pragma unroll
                    for (int hh = 0; hh < 2; hh++) {
                        const int m = row0 + hh*8;
                        const int b = m >> 11, ltok = m & (LQ-1);
                        const size_t bh = (size_t)(b*HQ + h);
                        const float v0 = cc[hh*2], v1 = cc[hh*2+1];
                        if (part == 0) {
                            *reinterpret_cast<uint32_t*>(g_qh + (bh*LQ + ltok)*DH + e) =
                                pack_half2(v0 * qs, v1 * qs);
                        } else if (part == 1) {
                            *reinterpret_cast<uint32_t*>(g_kh + (bh*LQ + ltok)*DH + e) =
                                pack_half2(v0, v1);
                        } else {
                            *reinterpret_cast<uint32_t*>(g_vh + (bh*LQ + ltok)*DH + e) =
                                pack_half2(v0, v1);
                        }
                    }
                } else {
                    const int col = colBase + cloc;
                    *reinterpret_cast<float2*>(OUT + (size_t)row0*EQ + col)     = make_float2(cc[0], cc[1]);
                    *reinterpret_cast<float2*>(OUT + (size_t)(row0+8)*EQ + col) = make_float2(cc[2], cc[3]);
                }
            }
        }
    }
}

// ---------------------------------------------------------------------------
// x -> fp16 (elementwise, vectorized)
// ---------------------------------------------------------------------------
__global__ void __launch_bounds__(256) conv_x_k(const float* __restrict__ x)
{
    const int i = blockIdx.x * 256 + threadIdx.x;
    float4 v = reinterpret_cast<const float4*>(x)[i];
    uint32_t* o = reinterpret_cast<uint32_t*>(g_xh);
    o[2*i]   = pack_half2(v.x, v.y);
    o[2*i+1] = pack_half2(v.z, v.w);
}

// ---------------------------------------------------------------------------
// Weight transpose + fp16 convert (tiny)
// ---------------------------------------------------------------------------
template<int WM>
__global__ void __launch_bounds__(256) transpose_k(const float* __restrict__ src)
{
    constexpr int R = (WM == 0) ? EQ : HQ*EQ;
    constexpr int C = (WM == 0) ? 3*HQ*EQ : EQ;
    __half* dst = (WM == 0) ? g_wqkvTh : g_woutTh;
    __shared__ float t[32][33];
    const int c0 = blockIdx.x * 32, r0 = blockIdx.y * 32;
    const int tx = threadIdx.x & 31, ty = threadIdx.x >> 5;
    #pragma unroll
    for (int i = 0; i < 4; i++)
        t[ty + i*8][tx] = src[(size_t)(r0 + ty + i*8) * C + c0 + tx];
    __syncthreads();
    #pragma unroll
    for (int i = 0; i < 4; i++)
        dst[(size_t)(c0 + ty + i*8) * R + r0 + tx] = __float2half_rn(t[tx][ty + i*8]);
}

// ---------------------------------------------------------------------------
// Launch
// ---------------------------------------------------------------------------
#define SMEM_256 ((AS_H + 256*SSTH) * 2 * 3)   // 92160 B
#define SMEM_128 ((AS_H + 128*SSTH) * 2 * 3)   // 61440 B

extern "C" void kernel_launch(void* const* d_in, const int* in_sizes, int n_in,
                              void* d_out, int out_size)
{
    const float* x    = (const float*)d_in[0];   // [4,2048,256]
    const float* Wqkv = (const float*)d_in[1];   // [256,6144]
    const float* Wout = (const float*)d_in[2];   // [2048,256]
    float* out = (float*)d_out;                  // [4,2048,256]

    cudaFuncSetAttribute((const void*)tgemm<0,256>, cudaFuncAttributeMaxDynamicSharedMemorySize, SMEM_256);
    cudaFuncSetAttribute((const void*)tgemm<3,128>, cudaFuncAttributeMaxDynamicSharedMemorySize, SMEM_128);
    cudaFuncSetAttribute((const void*)flash_k,      cudaFuncAttributeMaxDynamicSharedMemorySize, FLASH_SMEM);

    conv_x_k<<<(BQ*LQ*EQ)/1024, 256>>>(x);
    transpose_k<0><<<dim3((3*HQ*EQ)/32, EQ/32), 256>>>(Wqkv);
    transpose_k<1><<<dim3(EQ/32, (HQ*EQ)/32), 256>>>(Wout);

    // 1) QKV projection + scatter (q scaled by 1/16*log2e, k, v natural)
    tgemm<0,256><<<dim3((3*HQ*EQ)/256, (BQ*LQ)/BMT, 1), 256, SMEM_256>>>(nullptr);

    // 2) fused flash attention -> g_atth (3-region KV ring, 1 sync/tile)
    flash_k<<<dim3(LQ/RQ, BQ*HQ), 256, FLASH_SMEM>>>();

    // 3) out = att @ W_out
    tgemm<3,128><<<dim3(EQ/128, (BQ*LQ)/BMT, 1), 256, SMEM_128>>>(out);
}

// round 16
// speedup vs baseline: 1.0642x; 1.0642x over previous
#include <cuda_runtime.h>
#include <cuda_fp16.h>
#include <cstdint>
#include <math.h>

#define BQ 4
#define LQ 2048
#define EQ 256
#define HQ 8
#define DH 256     // head dim

// ---------------------------------------------------------------------------
// Scratch (allocation-free device globals, ~132 MB)
// ---------------------------------------------------------------------------
__device__ __half g_xh   [BQ*LQ*EQ];              // x in fp16
__device__ __half g_qh   [BQ*HQ*LQ*DH];           // [bh][l][e], pre-scaled 1/16*log2e
__device__ __half g_kh   [BQ*HQ*LQ*DH];           // [bh][l][e]
__device__ __half g_vh   [BQ*HQ*LQ*DH];           // [bh][l][e] (natural)
__device__ __half g_atth [(size_t)BQ*LQ*HQ*EQ];   // [b][l][h*E+e]
__device__ __half g_wqkvTh[3*HQ*EQ*EQ];           // [6144][256]
__device__ __half g_woutTh[EQ*HQ*EQ];             // [256][2048]

static __device__ __forceinline__ uint32_t smem_u32(const void* p) {
    uint32_t a;
    asm("{ .reg .u64 t; cvta.to.shared.u64 t, %1; cvt.u32.u64 %0, t; }" : "=r"(a) : "l"(p));
    return a;
}
static __device__ __forceinline__ float ex2f(float x) {
    float r; asm("ex2.approx.f32 %0, %1;" : "=f"(r) : "f"(x)); return r;
}
// pack two fp32 -> one b32 reg of f16x2 (lo = a, hi = b)
static __device__ __forceinline__ uint32_t pack_half2(float a, float b) {
    uint32_t u;
    asm("cvt.rn.f16x2.f32 %0, %1, %2;" : "=r"(u) : "f"(b), "f"(a));
    return u;
}
#define CP_ASYNC16(d, s) \
    asm volatile("cp.async.cg.shared.global [%0], [%1], 16;" :: "r"(d), "l"(s))
#define CP_COMMIT() asm volatile("cp.async.commit_group;" ::: "memory")
template<int N> static __device__ __forceinline__ void cp_wait() {
    asm volatile("cp.async.wait_group %0;" :: "n"(N) : "memory");
}
#define LDSM4(r0, r1, r2, r3, a)                                              \
    asm volatile("ldmatrix.sync.aligned.m8n8.x4.shared.b16 {%0,%1,%2,%3}, [%4];" \
        : "=r"(r0), "=r"(r1), "=r"(r2), "=r"(r3) : "r"(a))
#define LDSM4T(r0, r1, r2, r3, a)                                             \
    asm volatile("ldmatrix.sync.aligned.m8n8.x4.trans.shared.b16 {%0,%1,%2,%3}, [%4];" \
        : "=r"(r0), "=r"(r1), "=r"(r2), "=r"(r3) : "r"(a))
#define MMA_F16(c, a0, a1, a2, a3, b0, b1)                                    \
    asm volatile("mma.sync.aligned.m16n8k16.row.col.f32.f16.f16.f32 "         \
        "{%0,%1,%2,%3}, {%4,%5,%6,%7}, {%8,%9}, {%0,%1,%2,%3};"               \
        : "+f"((c)[0]), "+f"((c)[1]), "+f"((c)[2]), "+f"((c)[3])              \
        : "r"(a0), "r"(a1), "r"(a2), "r"(a3), "r"(b0), "r"(b1))

// ---------------------------------------------------------------------------
// Flash attention (R13 version — best known): one CTA = (bh, 128 q rows).
// 256 thr, 8 warps x 16 rows. Q frags in registers; K/V streamed in 64-row
// double-buffered tiles (issue BEFORE wait: copy off the critical path).
// Fixed-base softmax p = exp2(s); 4-chunk S->exp->O interleave per tile.
// ---------------------------------------------------------------------------
#define RQ 128         // q rows per CTA
#define TKV 64         // kv rows per tile
#define SST 264        // smem row stride (halves)
#define QH (RQ*SST)    // Q halves
#define KVH (TKV*SST)  // K or V tile halves
#define FLASH_SMEM ((QH + 4*KVH) * 2)   // 202752 B

__global__ void __launch_bounds__(256)
flash_k()
{
    extern __shared__ __align__(16) __half sm[];
    const int bh = blockIdx.y;
    const int qb = blockIdx.x;
    const __half* Qg = g_qh + (size_t)bh*LQ*DH + (size_t)qb*RQ*DH;
    const __half* Kg = g_kh + (size_t)bh*LQ*DH;
    const __half* Vg = g_vh + (size_t)bh*LQ*DH;

    const int tid = threadIdx.x;
    const uint32_t sbase = smem_u32(sm);

    // ---- load Q (async, group 0) ----
    #pragma unroll
    for (int j = 0; j < 16; j++) {
        const int idx = tid + 256*j;
        const int row = idx >> 5, ch = idx & 31;
        CP_ASYNC16(sbase + 2*(uint32_t)(row*SST + ch*8), Qg + (size_t)row*DH + ch*8);
    }
    CP_COMMIT();

    auto issueKV = [&](int t, int st) {
        const int kv0 = t * TKV;
        const uint32_t kb = sbase + 2*(uint32_t)(QH + st*2*KVH);
        #pragma unroll
        for (int j = 0; j < 8; j++) {
            const int idx = tid + 256*j;
            const int row = idx >> 5, ch = idx & 31;
            CP_ASYNC16(kb + 2*(uint32_t)(row*SST + ch*8),
                       Kg + (size_t)(kv0 + row)*DH + ch*8);
            CP_ASYNC16(kb + 2*(uint32_t)(KVH + row*SST + ch*8),
                       Vg + (size_t)(kv0 + row)*DH + ch*8);
        }
    };
    issueKV(0, 0);
    CP_COMMIT();

    const int wid = tid >> 5, lane = tid & 31;
    const int grp = lane >> 2, tig = lane & 3;

    const uint32_t aoff = (uint32_t)((wid*16 + (lane & 15)) * SST + (lane >> 4) * 8);
    const uint32_t boff = (uint32_t)(((lane & 7) + ((lane & 16) >> 1)) * SST + (lane & 8));

    // ---- hoist Q fragments into registers (Q is tile-invariant) ----
    cp_wait<1>();            // group0 (Q) complete; KV0 may still be in flight
    __syncthreads();
    uint32_t qf[16][4];
    #pragma unroll
    for (int ks = 0; ks < 16; ks++)
        LDSM4(qf[ks][0], qf[ks][1], qf[ks][2], qf[ks][3],
              sbase + 2*(aoff + (uint32_t)(ks*16)));

    float o[32][4];
    #pragma unroll
    for (int j = 0; j < 32; j++)
        #pragma unroll
        for (int i = 0; i < 4; i++) o[j][i] = 0.f;
    float l0 = 0.f, l1 = 0.f;     // per-thread partial row sums

    const int NT = LQ / TKV;   // 32
    for (int t = 0; t < NT; t++) {
        if (t + 1 < NT) { issueKV(t + 1, (t + 1) & 1); CP_COMMIT(); cp_wait<1>(); }
        else            { cp_wait<0>(); }
        __syncthreads();

        const uint32_t kb = sbase + 2*(uint32_t)(QH + (t & 1)*2*KVH) + 2*boff;
        const uint32_t vb = kb + 2*(uint32_t)KVH;

        // ---- 4 independent 16-KV-row chunks: S -> exp -> pack -> O ----
        #pragma unroll
        for (int kt = 0; kt < 4; kt++) {
            float s0[4] = {0.f, 0.f, 0.f, 0.f};
            float s1[4] = {0.f, 0.f, 0.f, 0.f};
            #pragma unroll
            for (int ks = 0; ks < 16; ks++) {
                uint32_t b0, b1, b2, b3;
                LDSM4(b0, b1, b2, b3, kb + 2*(uint32_t)(kt*16*SST + ks*16));
                MMA_F16(s0, qf[ks][0], qf[ks][1], qf[ks][2], qf[ks][3], b0, b1);
                MMA_F16(s1, qf[ks][0], qf[ks][1], qf[ks][2], qf[ks][3], b2, b3);
            }

            s0[0] = ex2f(s0[0]);  l0 += s0[0];
            s0[1] = ex2f(s0[1]);  l0 += s0[1];
            s0[2] = ex2f(s0[2]);  l1 += s0[2];
            s0[3] = ex2f(s0[3]);  l1 += s0[3];
            s1[0] = ex2f(s1[0]);  l0 += s1[0];
            s1[1] = ex2f(s1[1]);  l0 += s1[1];
            s1[2] = ex2f(s1[2]);  l1 += s1[2];
            s1[3] = ex2f(s1[3]);  l1 += s1[3];

            const uint32_t a0 = pack_half2(s0[0], s0[1]);
            const uint32_t a1 = pack_half2(s0[2], s0[3]);
            const uint32_t a2 = pack_half2(s1[0], s1[1]);
            const uint32_t a3 = pack_half2(s1[2], s1[3]);

            #pragma unroll
            for (int eg = 0; eg < 16; eg++) {
                uint32_t v0, v1, v2, v3;
                LDSM4T(v0, v1, v2, v3, vb + 2*(uint32_t)(kt*16*SST + eg*16));
                MMA_F16(o[2*eg],     a0, a1, a2, a3, v0, v2);
                MMA_F16(o[2*eg + 1], a0, a1, a2, a3, v1, v3);
            }
        }
        __syncthreads();
    }

    // ---- single final row-sum reduction across the quad ----
    l0 += __shfl_xor_sync(0xffffffffu, l0, 1);
    l0 += __shfl_xor_sync(0xffffffffu, l0, 2);
    l1 += __shfl_xor_sync(0xffffffffu, l1, 1);
    l1 += __shfl_xor_sync(0xffffffffu, l1, 2);
    const float rl0 = 1.f / l0, rl1 = 1.f / l1;

    // ---- epilogue: O /= l, write fp16 concat layout ----
    const int b = bh >> 3, h = bh & 7;
    const int tok0 = qb*RQ + wid*16 + grp;
    uint32_t* base0 = reinterpret_cast<uint32_t*>(
        g_atth + ((size_t)(b*LQ + tok0))*(HQ*EQ) + h*DH);
    uint32_t* base1 = reinterpret_cast<uint32_t*>(
        g_atth + ((size_t)(b*LQ + tok0 + 8))*(HQ*EQ) + h*DH);
    #pragma unroll
    for (int j = 0; j < 32; j++) {
        const int c2 = (j*8 + tig*2) >> 1;   // half2 index within head slice
        base0[c2] = pack_half2(o[j][0]*rl0, o[j][1]*rl0);
        base1[c2] = pack_half2(o[j][2]*rl1, o[j][3]*rl1);
    }
}

// ---------------------------------------------------------------------------
// fp16 mma GEMM: C[M,N] = A[M,K] @ B[N,K]^T  -- 3-stage pipeline
// MODE 0 (BNTT=256): qkv = xh @ WqkvTh^T; epilogue stages C through smem and
//   writes full contiguous 512B head-rows (coalesced), scale folded in.
// MODE 3 (BNTT=128): out = att @ WoutTh^T -> fp32 (direct frag epilogue)
// ---------------------------------------------------------------------------
#define BMT 128
#define BKT 32
#define SSTH 40
#define AS_H (128*SSTH)

template<int MODE, int BNTT>
__global__ void __launch_bounds__(256)
tgemm(float* __restrict__ OUT)
{
    constexpr int NT2   = BNTT / 64;
    constexpr int BS_H  = BNTT * SSTH;
    constexpr int STG_B = (AS_H + BS_H) * 2;

    extern __shared__ __align__(16) __half smh[];

    const __half* A; const __half* B; int lda, ldb, K;
    if (MODE == 0) { A = g_xh;   lda = EQ;    B = g_wqkvTh; ldb = EQ;    K = EQ; }
    else           { A = g_atth; lda = HQ*EQ; B = g_woutTh; ldb = HQ*EQ; K = HQ*EQ; }

    const int tid  = threadIdx.x;
    const int rowBase = blockIdx.y * BMT;
    const int colBase = blockIdx.x * BNTT;

    const int lrow  = tid >> 2;
    const int lslot = tid & 3;
    const __half* Ag = A + (size_t)(rowBase + lrow) * lda + lslot * 8;
    const __half* Bg = B + (size_t)(colBase + lrow) * ldb + lslot * 8;
    const uint32_t sbase = smem_u32(smh);
    const uint32_t soff  = (uint32_t)(lrow * SSTH + lslot * 8) * 2;

    const int wid  = tid >> 5, lane = tid & 31;
    const int grp  = lane >> 2, tig = lane & 3;
    const int wm   = (wid >> 2) * 64;
    const int wn   = (wid & 3) * (BNTT / 4);

    const uint32_t aoffh = (uint32_t)((wm + (lane & 15)) * SSTH + ((lane >> 4) * 8));
    const uint32_t boffh = (uint32_t)((wn + (lane & 7) + ((lane & 16) >> 1)) * SSTH + (lane & 8));

    float c[4][NT2][2][4];
    #pragma unroll
    for (int mt = 0; mt < 4; mt++)
        #pragma unroll
        for (int n2 = 0; n2 < NT2; n2++)
            #pragma unroll
            for (int s = 0; s < 2; s++)
                #pragma unroll
                for (int i = 0; i < 4; i++) c[mt][n2][s][i] = 0.f;

    const int nk = K / BKT;

    auto issue = [&](int kt, int st) {
        const int k0 = kt * BKT;
        const uint32_t dA = sbase + st * STG_B + soff;
        CP_ASYNC16(dA,             Ag + k0);
        CP_ASYNC16(dA + 2*64*SSTH, Ag + k0 + (size_t)64 * lda);
        const uint32_t dB = sbase + st * STG_B + 2*AS_H + soff;
        #pragma unroll
        for (int i = 0; i < BNTT/64; i++)
            CP_ASYNC16(dB + i*2*64*SSTH, Bg + k0 + (size_t)(64*i) * ldb);
    };
    auto compute = [&](int st) {
        const uint32_t ab = sbase + st * STG_B + 2*aoffh;
        const uint32_t bb = sbase + st * STG_B + 2*AS_H + 2*boffh;
        #pragma unroll
        for (int ks = 0; ks < 2; ks++) {
            uint32_t af[4][4];
            #pragma unroll
            for (int mt = 0; mt < 4; mt++)
                LDSM4(af[mt][0], af[mt][1], af[mt][2], af[mt][3],
                      ab + 2*(uint32_t)(mt*16*SSTH + ks*16));
            #pragma unroll
            for (int n2 = 0; n2 < NT2; n2++) {
                uint32_t b0, b1, b2, b3;
                LDSM4(b0, b1, b2, b3, bb + 2*(uint32_t)(n2*16*SSTH + ks*16));
                #pragma unroll
                for (int mt = 0; mt < 4; mt++) {
                    MMA_F16(c[mt][n2][0], af[mt][0], af[mt][1], af[mt][2], af[mt][3], b0, b1);
                    MMA_F16(c[mt][n2][1], af[mt][0], af[mt][1], af[mt][2], af[mt][3], b2, b3);
                }
            }
        }
    };

    // 3-stage pipeline: stages kt%3; one sync per iteration.
    issue(0, 0); CP_COMMIT();
    issue(1, 1); CP_COMMIT();
    for (int kt = 0; kt < nk; kt++) {
        if (kt == nk - 1) cp_wait<0>(); else cp_wait<1>();
        __syncthreads();
        if (kt + 2 < nk) { issue(kt + 2, (kt + 2) % 3); CP_COMMIT(); }
        compute(kt % 3);
    }

    if (MODE == 0) {
        // ---- smem-staged epilogue: C tile -> smem fp16 -> coalesced rows ----
        const int part = colBase >> 11;           // 0=q, 1=k, 2=v
        const int h    = (colBase >> 8) & 7;
        const float qs = (part == 0) ? 0.0625f * 1.44269504f : 1.0f;

        __syncthreads();    // mainloop smem reads complete before overwrite
        #pragma unroll
        for (int mt = 0; mt < 4; mt++)
            #pragma unroll
            for (int n2 = 0; n2 < NT2; n2++)
                #pragma unroll
                for (int s = 0; s < 2; s++) {
                    const int r0 = wm + mt*16 + grp;
                    const int cl = wn + (n2*2 + s)*8 + tig*2;
                    const float* cc = c[mt][n2][s];
                    *reinterpret_cast<uint32_t*>(smh + r0*264 + cl) =
                        pack_half2(cc[0]*qs, cc[1]*qs);
                    *reinterpret_cast<uint32_t*>(smh + (r0+8)*264 + cl) =
                        pack_half2(cc[2]*qs, cc[3]*qs);
                }
        __syncthreads();

        __half* dstbase = (part == 0) ? g_qh : (part == 1) ? g_kh : g_vh;
        #pragma unroll
        for (int j = 0; j < 16; j++) {
            const int idx = tid + 256*j;
            const int row = idx >> 5, ch = idx & 31;   // 128 rows x 32 16B-chunks
            const int m = rowBase + row;
            const int b = m >> 11, ltok = m & (LQ-1);
            const size_t bh = (size_t)(b*HQ + h);
            uint4 v = *reinterpret_cast<const uint4*>(smh + row*264 + ch*8);
            *reinterpret_cast<uint4*>(dstbase + (bh*LQ + ltok)*DH + ch*8) = v;
        }
    } else {
        #pragma unroll
        for (int mt = 0; mt < 4; mt++)
            #pragma unroll
            for (int n2 = 0; n2 < NT2; n2++)
                #pragma unroll
                for (int s = 0; s < 2; s++) {
                    const int row0 = rowBase + wm + mt*16 + grp;
                    const int col  = colBase + wn + (n2*2 + s)*8 + tig*2;
                    const float* cc = c[mt][n2][s];
                    *reinterpret_cast<float2*>(OUT + (size_t)row0*EQ + col)     = make_float2(cc[0], cc[1]);
                    *reinterpret_cast<float2*>(OUT + (size_t)(row0+8)*EQ + col) = make_float2(cc[2], cc[3]);
                }
    }
}

// ---------------------------------------------------------------------------
// x -> fp16 (elementwise, vectorized)
// ---------------------------------------------------------------------------
__global__ void __launch_bounds__(256) conv_x_k(const float* __restrict__ x)
{
    const int i = blockIdx.x * 256 + threadIdx.x;
    float4 v = reinterpret_cast<const float4*>(x)[i];
    uint32_t* o = reinterpret_cast<uint32_t*>(g_xh);
    o[2*i]   = pack_half2(v.x, v.y);
    o[2*i+1] = pack_half2(v.z, v.w);
}

// ---------------------------------------------------------------------------
// Weight transpose + fp16 convert (tiny)
// ---------------------------------------------------------------------------
template<int WM>
__global__ void __launch_bounds__(256) transpose_k(const float* __restrict__ src)
{
    constexpr int R = (WM == 0) ? EQ : HQ*EQ;
    constexpr int C = (WM == 0) ? 3*HQ*EQ : EQ;
    __half* dst = (WM == 0) ? g_wqkvTh : g_woutTh;
    __shared__ float t[32][33];
    const int c0 = blockIdx.x * 32, r0 = blockIdx.y * 32;
    const int tx = threadIdx.x & 31, ty = threadIdx.x >> 5;
    #pragma unroll
    for (int i = 0; i < 4; i++)
        t[ty + i*8][tx] = src[(size_t)(r0 + ty + i*8) * C + c0 + tx];
    __syncthreads();
    #pragma unroll
    for (int i = 0; i < 4; i++)
        dst[(size_t)(c0 + ty + i*8) * R + r0 + tx] = __float2half_rn(t[tx][ty + i*8]);
}

// ---------------------------------------------------------------------------
// Launch
// ---------------------------------------------------------------------------
#define SMEM_256 ((AS_H + 256*SSTH) * 2 * 3)   // 92160 B
#define SMEM_128 ((AS_H + 128*SSTH) * 2 * 3)   // 61440 B

extern "C" void kernel_launch(void* const* d_in, const int* in_sizes, int n_in,
                              void* d_out, int out_size)
{
    const float* x    = (const float*)d_in[0];   // [4,2048,256]
    const float* Wqkv = (const float*)d_in[1];   // [256,6144]
    const float* Wout = (const float*)d_in[2];   // [2048,256]
    float* out = (float*)d_out;                  // [4,2048,256]

    cudaFuncSetAttribute((const void*)tgemm<0,256>, cudaFuncAttributeMaxDynamicSharedMemorySize, SMEM_256);
    cudaFuncSetAttribute((const void*)tgemm<3,128>, cudaFuncAttributeMaxDynamicSharedMemorySize, SMEM_128);
    cudaFuncSetAttribute((const void*)flash_k,      cudaFuncAttributeMaxDynamicSharedMemorySize, FLASH_SMEM);

    conv_x_k<<<(BQ*LQ*EQ)/1024, 256>>>(x);
    transpose_k<0><<<dim3((3*HQ*EQ)/32, EQ/32), 256>>>(Wqkv);
    transpose_k<1><<<dim3(EQ/32, (HQ*EQ)/32), 256>>>(Wout);

    // 1) QKV projection + scatter (coalesced smem-staged epilogue)
    tgemm<0,256><<<dim3((3*HQ*EQ)/256, (BQ*LQ)/BMT, 1), 256, SMEM_256>>>(nullptr);

    // 2) fused flash attention -> g_atth (R13 version: 2-stage, issue-first)
    flash_k<<<dim3(LQ/RQ, BQ*HQ), 256, FLASH_SMEM>>>();

    // 3) out = att @ W_out
    tgemm<3,128><<<dim3(EQ/128, (BQ*LQ)/BMT, 1), 256, SMEM_128>>>(out);
}